// round 7
// baseline (speedup 1.0000x reference)
#include <cuda_runtime.h>
#include <math.h>
#include <stdint.h>

#define KC 4
#define D  8

#define LOG_2PI 1.8378770664093453f
#define LN2F    0.6931471805599453f

typedef unsigned long long ull;

__device__ __forceinline__ float rcp_a(float x)  { float y; asm("rcp.approx.f32 %0, %1;"   : "=f"(y) : "f"(x)); return y; }
__device__ __forceinline__ float rsq_a(float x)  { float y; asm("rsqrt.approx.f32 %0, %1;" : "=f"(y) : "f"(x)); return y; }
__device__ __forceinline__ float lg2_a(float x)  { float y; asm("lg2.approx.f32 %0, %1;"   : "=f"(y) : "f"(x)); return y; }

// ---------------------------------------------------------------------------
// Hot-path params. Coefficients row-padded for LDS.128: row r of component j
// lives at sLp[j][8r .. 8r+r] (scaled by 1/sqrt2 so 0.5*M is folded in).
// ---------------------------------------------------------------------------
struct __align__(16) HotP {
    float sLp[KC][64];     // row-padded scaled Linv (8 floats per row)
    float nb[KC][D];       // -bias/sqrt2
    float cf[KC];          // 0.5*D*log(2pi) - half_log_det
    int   active[KC];      // class i participates (indices[i] != 0)
    int   tmask[KC];       // one-hot bit of target component ci = indices[i]
    int   emask[KC];       // bits {j != i : indices[j] == indices[i]}
    int   cnt;
    int   _pad;
};

__device__ HotP         g_h;
__device__ double       g_sum;     // zero at module load; self-reset each launch
__device__ unsigned int g_ticket;

// ---------------------------------------------------------------------------
// Kernel 1: setup — one thread per component, approx-MUFU rcp/rsqrt/lg2.
// ---------------------------------------------------------------------------
__global__ void setup_kernel(const float* __restrict__ means,
                             const float* __restrict__ covs,
                             const int*   __restrict__ indices)
{
    const int j = threadIdx.x;
    if (blockIdx.x != 0 || j >= KC) return;

    const float INV_SQRT2 = 0.70710678118654752f;

    float L[D][D], Li[D][D];
    const float* a = covs + j * D * D;
    // Cholesky: cov = L * L^T  (approx rsqrt/rcp; cov eigmin >= 0.5)
    #pragma unroll
    for (int r = 0; r < D; ++r) {
        #pragma unroll
        for (int c = 0; c <= r; ++c) {
            float s = a[r * D + c];
            #pragma unroll
            for (int k = 0; k < c; ++k) s -= L[r][k] * L[c][k];
            if (c == r) L[r][c] = s * rsq_a(s);
            else        L[r][c] = s * rcp_a(L[c][c]);
        }
    }
    // Invert lower-triangular L; half-log-det via lg2
    float hld = 0.0f;
    #pragma unroll
    for (int c = 0; c < D; ++c) {
        Li[c][c] = rcp_a(L[c][c]);
        #pragma unroll
        for (int r = c + 1; r < D; ++r) {
            float s = 0.0f;
            #pragma unroll
            for (int k = c; k < r; ++k) s += L[r][k] * Li[k][c];
            Li[r][c] = -s * rcp_a(L[r][r]);
        }
        hld += lg2_a(L[c][c]);
    }
    hld *= LN2F;

    #pragma unroll
    for (int r = 0; r < D; ++r)
        #pragma unroll
        for (int c = 0; c < D; ++c)
            g_h.sLp[j][8 * r + c] = (c <= r) ? Li[r][c] * INV_SQRT2 : 0.0f;
    #pragma unroll
    for (int r = 0; r < D; ++r) {
        float s = 0.0f;
        #pragma unroll
        for (int c = 0; c <= r; ++c) s += Li[r][c] * means[j * D + c];
        g_h.nb[j][r] = -s * INV_SQRT2;
    }
    g_h.cf[j] = 0.5f * (float)D * LOG_2PI - hld;

    if (j == 0) {
        g_sum = 0.0;
        g_ticket = 0u;
        int cnt = 0;
        for (int i = 0; i < KC; ++i) {
            int ci = indices[i];
            int act = (ci != 0);
            g_h.active[i] = act;
            if (act) cnt++;
            int ti = ci; if (ti < 0) ti = 0; if (ti > KC - 1) ti = KC - 1;
            g_h.tmask[i] = 1 << ti;
            int em = 0;
            for (int jj = 0; jj < KC; ++jj)
                if (indices[jj] == ci && jj != i) em |= (1 << jj);
            g_h.emask[i] = em;
        }
        g_h.cnt = cnt;
    }
}

// ---------------------------------------------------------------------------
// Kernel 2: fused hot path + finalize. Proven scalar body; coefficient rows
// loaded via LDS.128 (issue-slot diet); ticket pattern so the last-finishing
// block finalizes and self-resets for graph replay.
// ---------------------------------------------------------------------------
__global__ void __launch_bounds__(256) lp_kernel(const float* __restrict__ pred, int N,
                                                 float* __restrict__ out)
{
    __shared__ HotP sh;
    {
        const int nq = (int)(sizeof(HotP) / 8);
        const ull* src = (const ull*)&g_h;
        ull* dst = (ull*)&sh;
        for (int u = threadIdx.x; u < nq; u += blockDim.x) dst[u] = src[u];
    }
    __syncthreads();

    const int N4 = N >> 2;
    const int tid = blockIdx.x * blockDim.x + threadIdx.x;
    const int stride = gridDim.x * blockDim.x;

    float acc = 0.0f;

    for (int v = tid; v < N4; v += stride) {
        #pragma unroll
        for (int i = 0; i < KC; ++i) {
            if (!sh.active[i]) continue;
            const float4* base = (const float4*)pred + (size_t)i * D * N4;
            float4 x[D];
            #pragma unroll
            for (int dd = 0; dd < D; ++dd)
                x[dd] = base[(size_t)dd * N4 + v];

            float lp[KC][4];
            #pragma unroll
            for (int j = 0; j < KC; ++j) {
                float M0 = sh.cf[j], M1 = M0, M2 = M0, M3 = M0;
                #pragma unroll
                for (int r = 0; r < D; ++r) {
                    float nb = sh.nb[j][r];
                    float s0 = nb, s1 = nb, s2 = nb, s3 = nb;
                    // vectorized coefficient loads (row-padded, 16B aligned)
                    float cr[8];
                    {
                        float4 ca = *(const float4*)&sh.sLp[j][8 * r];
                        cr[0] = ca.x; cr[1] = ca.y; cr[2] = ca.z; cr[3] = ca.w;
                    }
                    if (r >= 4) {
                        float4 cb = *(const float4*)&sh.sLp[j][8 * r + 4];
                        cr[4] = cb.x; cr[5] = cb.y; cr[6] = cb.z; cr[7] = cb.w;
                    }
                    #pragma unroll
                    for (int c = 0; c <= r; ++c) {
                        float l = cr[c];
                        s0 = fmaf(l, x[c].x, s0);
                        s1 = fmaf(l, x[c].y, s1);
                        s2 = fmaf(l, x[c].z, s2);
                        s3 = fmaf(l, x[c].w, s3);
                    }
                    M0 = fmaf(s0, s0, M0);
                    M1 = fmaf(s1, s1, M1);
                    M2 = fmaf(s2, s2, M2);
                    M3 = fmaf(s3, s3, M3);
                }
                lp[j][0] = M0; lp[j][1] = M1; lp[j][2] = M2; lp[j][3] = M3;
            }

            const int tm = sh.tmask[i];
            const int em = sh.emask[i];
            #pragma unroll
            for (int s = 0; s < 4; ++s) {
                float e0 = __expf(lp[0][s]);
                float e1 = __expf(lp[1][s]);
                float e2 = __expf(lp[2][s]);
                float e3 = __expf(lp[3][s]);
                // tot_ll + exp(target) == 1e-8 + sum_all - sum_{j!=i, cj==ci}
                float tot = 1e-8f + ((e0 + e1) + (e2 + e3));
                if (em) {
                    tot -= (em & 1) ? e0 : 0.0f;
                    tot -= (em & 2) ? e1 : 0.0f;
                    tot -= (em & 4) ? e2 : 0.0f;
                    tot -= (em & 8) ? e3 : 0.0f;
                }
                float tll = (tm & 1) ? lp[0][s]
                          : (tm & 2) ? lp[1][s]
                          : (tm & 4) ? lp[2][s] : lp[3][s];
                acc += tll - __logf(tot);
            }
        }
    }

    // fp64 block reduction
    double dacc = (double)acc;
    #pragma unroll
    for (int off = 16; off > 0; off >>= 1)
        dacc += __shfl_down_sync(0xffffffffu, dacc, off);
    __shared__ double wsum[8];
    __shared__ unsigned int slast;
    int lane = threadIdx.x & 31;
    int w = threadIdx.x >> 5;
    if (lane == 0) wsum[w] = dacc;
    __syncthreads();
    if (w == 0) {
        int nwarp = blockDim.x >> 5;
        double b = (lane < nwarp) ? wsum[lane] : 0.0;
        #pragma unroll
        for (int off = 4; off > 0; off >>= 1)
            b += __shfl_down_sync(0xffffffffu, b, off);
        if (lane == 0) {
            atomicAdd(&g_sum, b);
            __threadfence();
            unsigned int t = atomicAdd(&g_ticket, 1u);
            slast = (t == gridDim.x - 1) ? 1u : 0u;
        }
    }
    __syncthreads();

    // Last block: tail samples (N%4) + finalize + self-reset for graph replay.
    if (slast && threadIdx.x == 0) {
        double s = atomicAdd(&g_sum, 0.0);
        const int n0 = (N >> 2) << 2;
        for (int n = n0; n < N; ++n) {
            for (int i = 0; i < KC; ++i) {
                if (!sh.active[i]) continue;
                const float* base = pred + (size_t)i * D * N;
                float lp[KC];
                for (int j = 0; j < KC; ++j) {
                    float M = sh.cf[j];
                    for (int r = 0; r < D; ++r) {
                        float sr = sh.nb[j][r];
                        for (int c = 0; c <= r; ++c)
                            sr = fmaf(sh.sLp[j][8 * r + c], base[(size_t)c * N + n], sr);
                        M = fmaf(sr, sr, M);
                    }
                    lp[j] = M;
                }
                int tm = sh.tmask[i], em = sh.emask[i];
                float tot = 1e-8f, tll = 0.f;
                for (int j = 0; j < KC; ++j) {
                    float e = __expf(lp[j]);
                    if (!((em >> j) & 1)) tot += e;
                    if ((tm >> j) & 1) tll = lp[j];
                }
                s += (double)(tll - __logf(tot));
            }
        }
        int cnt = sh.cnt;
        float res = 0.0f;
        if (cnt > 0 && N > 0)
            res = (float)(-s / ((double)N * (double)cnt));
        out[0] = res;
        // reset accumulators for the next graph replay
        g_sum = 0.0;
        g_ticket = 0u;
        __threadfence();
    }
}

// ---------------------------------------------------------------------------
extern "C" void kernel_launch(void* const* d_in, const int* in_sizes, int n_in,
                              void* d_out, int out_size)
{
    const float* pred    = (const float*)d_in[0];  // (K, d, N)
    const float* means   = (const float*)d_in[1];  // (K, d)
    const float* covs    = (const float*)d_in[2];  // (K, d, d)
    const int*   indices = (const int*)d_in[3];    // (K,)

    const int N = in_sizes[0] / (KC * D);

    setup_kernel<<<1, 32>>>(means, covs, indices);

    const int N4 = N >> 2;
    const int threads = 256;
    int blocks = (N4 + threads - 1) / threads;
    if (blocks < 1) blocks = 1;
    lp_kernel<<<blocks, threads>>>(pred, N, (float*)d_out);
}